// round 6
// baseline (speedup 1.0000x reference)
#include <cuda_runtime.h>
#include <cuda_bf16.h>
#include <math_constants.h>

#define NN 100000
#define EE 1600000
#define F_IN 256
#define HH 4
#define DD 32
#define CC 47
#define NEG_SLOPE 0.2f

#define BM 128
#define BN 128
#define BK 16

// ---------------- scratch (__device__ globals; no allocation) ----------------
__device__ float g_feat [NN * HH * CC];   // gemm output [N, H*od] (max 188 wide)
__device__ float g_out  [NN * HH * CC];   // aggregated output / next-layer input
__device__ float g_el   [NN * HH];        // [N,4] -> float4 per node
__device__ float g_er   [NN * HH];
__device__ float g_c    [NN * HH];        // c = m + log(den) per (node, head)
__device__ float g_alpha[EE * HH];        // CSR-ordered raw e per (pos, head)
__device__ int   g_deg  [NN];
__device__ int   g_cnt  [NN];
__device__ int   g_rowptr[NN + 1];
__device__ int   g_csrc [EE];             // src node per CSR position

// ====================== CSR build (once per launch) ======================
__global__ void __launch_bounds__(256)
zero2_kernel() {
    int i = blockIdx.x * blockDim.x + threadIdx.x;
    if (i < NN) { g_deg[i] = 0; g_cnt[i] = 0; }
}

__global__ void __launch_bounds__(256)
hist_kernel(const int* __restrict__ dst) {
    int e = blockIdx.x * blockDim.x + threadIdx.x;
    if (e < EE) atomicAdd(&g_deg[dst[e]], 1);
}

// single-block exclusive scan of g_deg -> g_rowptr
__global__ void __launch_bounds__(1024)
scan_kernel() {
    __shared__ int sh[1024];
    const int t = threadIdx.x;
    const int CH = (NN + 1023) / 1024;   // 98
    const int base = t * CH;
    int sum = 0;
    #pragma unroll 1
    for (int i = 0; i < CH; i++) {
        int idx = base + i;
        if (idx < NN) sum += g_deg[idx];
    }
    sh[t] = sum;
    __syncthreads();
    for (int o = 1; o < 1024; o <<= 1) {
        int v = (t >= o) ? sh[t - o] : 0;
        __syncthreads();
        sh[t] += v;
        __syncthreads();
    }
    int excl = (t == 0) ? 0 : sh[t - 1];
    #pragma unroll 1
    for (int i = 0; i < CH; i++) {
        int idx = base + i;
        if (idx < NN) { g_rowptr[idx] = excl; excl += g_deg[idx]; }
    }
    if (t == 1023) g_rowptr[NN] = sh[1023];
}

__global__ void __launch_bounds__(256)
scatter_kernel(const int* __restrict__ src, const int* __restrict__ dst) {
    int e = blockIdx.x * blockDim.x + threadIdx.x;
    if (e >= EE) return;
    int d = dst[e];
    int p = g_rowptr[d] + atomicAdd(&g_cnt[d], 1);
    g_csrc[p] = src[e];
}

// ====================== SGEMM: g_feat[M,N] = A[M,K] @ B[K,N] ======================
// 128x128 tile, BK=16, 256 threads, 8x8 per thread, double-buffered, FFMA2 via PTX.
__device__ __forceinline__ void load_tile(
    const float* __restrict__ A, const float* __restrict__ B,
    int M, int N, int K, int row0, int col0, int k0, int tid,
    float (* __restrict__ As)[BM + 2], float (* __restrict__ Bs)[BN]) {
    #pragma unroll
    for (int t = 0; t < 2; t++) {
        int fi = tid + t * 256;
        {   // A tile: 128 rows x 16 k, transposed into As[k][m]
            int row = fi >> 2, kq = fi & 3;
            int gr = row0 + row;
            float4 v = make_float4(0.f, 0.f, 0.f, 0.f);
            if (gr < M) v = *(const float4*)&A[(long)gr * K + k0 + kq * 4];
            As[kq * 4 + 0][row] = v.x;
            As[kq * 4 + 1][row] = v.y;
            As[kq * 4 + 2][row] = v.z;
            As[kq * 4 + 3][row] = v.w;
        }
        {   // B tile: 16 k x 128 n
            int krow = fi >> 5, nq = fi & 31;
            int gc = col0 + nq * 4;
            float4 v = make_float4(0.f, 0.f, 0.f, 0.f);
            if (gc < N) v = *(const float4*)&B[(long)(k0 + krow) * N + gc];
            *(float4*)&Bs[krow][nq * 4] = v;
        }
    }
}

__global__ void __launch_bounds__(256)
sgemm_kernel(const float* __restrict__ A, const float* __restrict__ B,
             int M, int N, int K) {
    __shared__ __align__(16) float As[2][BK][BM + 2];
    __shared__ __align__(16) float Bs[2][BK][BN];
    const int tid = threadIdx.x;
    const int tx = tid & 15;
    const int ty = tid >> 4;
    const int row0 = blockIdx.x * BM;
    const int col0 = blockIdx.y * BN;

    unsigned long long acc[4][8];
    #pragma unroll
    for (int r = 0; r < 4; r++)
        #pragma unroll
        for (int j = 0; j < 8; j++) acc[r][j] = 0ull;

    load_tile(A, B, M, N, K, row0, col0, 0, tid, As[0], Bs[0]);
    __syncthreads();

    int buf = 0;
    for (int k0 = 0; k0 < K; k0 += BK) {
        if (k0 + BK < K)
            load_tile(A, B, M, N, K, row0, col0, k0 + BK, tid, As[buf ^ 1], Bs[buf ^ 1]);
        #pragma unroll
        for (int kk = 0; kk < BK; kk++) {
            unsigned long long ap[4];
            #pragma unroll
            for (int r = 0; r < 4; r++)
                ap[r] = *(const unsigned long long*)&As[buf][kk][ty * 8 + r * 2];
            float4 b0 = *(const float4*)&Bs[buf][kk][tx * 8];
            float4 b1 = *(const float4*)&Bs[buf][kk][tx * 8 + 4];
            float bj[8] = {b0.x, b0.y, b0.z, b0.w, b1.x, b1.y, b1.z, b1.w};
            unsigned long long bd[8];
            #pragma unroll
            for (int j = 0; j < 8; j++)
                asm("mov.b64 %0, {%1, %1};" : "=l"(bd[j]) : "f"(bj[j]));
            #pragma unroll
            for (int r = 0; r < 4; r++)
                #pragma unroll
                for (int j = 0; j < 8; j++)
                    asm("fma.rn.f32x2 %0, %1, %2, %0;"
                        : "+l"(acc[r][j]) : "l"(ap[r]), "l"(bd[j]));
        }
        __syncthreads();
        buf ^= 1;
    }

    const int cbase = col0 + tx * 8;
    #pragma unroll
    for (int r = 0; r < 4; r++) {
        float lo[8], hi[8];
        #pragma unroll
        for (int j = 0; j < 8; j++)
            asm("mov.b64 {%0, %1}, %2;" : "=f"(lo[j]), "=f"(hi[j]) : "l"(acc[r][j]));
        int gr0 = row0 + ty * 8 + 2 * r;
        #pragma unroll
        for (int p = 0; p < 2; p++) {
            int gr = gr0 + p;
            if (gr >= M) continue;
            const float* c = p ? hi : lo;
            if (cbase + 7 < N) {
                *(float4*)&g_feat[(long)gr * N + cbase]     = make_float4(c[0], c[1], c[2], c[3]);
                *(float4*)&g_feat[(long)gr * N + cbase + 4] = make_float4(c[4], c[5], c[6], c[7]);
            } else {
                for (int jj = 0; jj < 8; jj++)
                    if (cbase + jj < N) g_feat[(long)gr * N + cbase + jj] = c[jj];
            }
        }
    }
}

// ====================== el/er per (node, head) ======================
__global__ void __launch_bounds__(256)
elr_kernel(const float* __restrict__ al, const float* __restrict__ ar, int od) {
    int idx = blockIdx.x * blockDim.x + threadIdx.x;   // n*H + h
    if (idx >= NN * HH) return;
    int n = idx >> 2, h = idx & 3;
    const float* f = g_feat + (long)n * HH * od + h * od;
    const float* alh = al + h * od;
    const float* arh = ar + h * od;
    float sl = 0.f, sr = 0.f;
    for (int d = 0; d < od; d++) { float v = f[d]; sl += v * alh[d]; sr += v * arh[d]; }
    g_el[idx] = sl;
    g_er[idx] = sr;
}

// ====================== single-sweep online softmax (warp per node) ======================
// Stores raw e into g_alpha and c = m + log(den) per (node, head) into g_c.
__device__ __forceinline__ float lrelu(float v) { return v > 0.f ? v : NEG_SLOPE * v; }

__global__ void __launch_bounds__(256)
attn_softmax_kernel() {
    int node = (blockIdx.x * blockDim.x + threadIdx.x) >> 5;
    int lane = threadIdx.x & 31;
    if (node >= NN) return;
    int r0 = g_rowptr[node], r1 = g_rowptr[node + 1];

    float4 erd = *(const float4*)&g_er[node * 4];

    float m0 = -CUDART_INF_F, m1 = -CUDART_INF_F, m2 = -CUDART_INF_F, m3 = -CUDART_INF_F;
    float s0 = 0.f, s1 = 0.f, s2 = 0.f, s3 = 0.f;

    for (int i = r0 + lane; i < r1; i += 32) {
        int s = g_csrc[i];
        float4 ev = *(const float4*)&g_el[s * 4];
        float4 e;
        e.x = lrelu(ev.x + erd.x);
        e.y = lrelu(ev.y + erd.y);
        e.z = lrelu(ev.z + erd.z);
        e.w = lrelu(ev.w + erd.w);
        *(float4*)&g_alpha[i * 4] = e;
        // online per-head update (m starts -inf; e finite so nm finite)
        float nm;
        nm = fmaxf(m0, e.x); s0 = s0 * __expf(fminf(m0 - nm, 0.f)) + __expf(e.x - nm); m0 = nm;
        nm = fmaxf(m1, e.y); s1 = s1 * __expf(fminf(m1 - nm, 0.f)) + __expf(e.y - nm); m1 = nm;
        nm = fmaxf(m2, e.z); s2 = s2 * __expf(fminf(m2 - nm, 0.f)) + __expf(e.z - nm); m2 = nm;
        nm = fmaxf(m3, e.w); s3 = s3 * __expf(fminf(m3 - nm, 0.f)) + __expf(e.w - nm); m3 = nm;
    }
    // warp max per head
    float M0 = m0, M1 = m1, M2 = m2, M3 = m3;
    #pragma unroll
    for (int o = 16; o > 0; o >>= 1) {
        M0 = fmaxf(M0, __shfl_xor_sync(0xffffffffu, M0, o));
        M1 = fmaxf(M1, __shfl_xor_sync(0xffffffffu, M1, o));
        M2 = fmaxf(M2, __shfl_xor_sync(0xffffffffu, M2, o));
        M3 = fmaxf(M3, __shfl_xor_sync(0xffffffffu, M3, o));
    }
    // rescale each lane's partial sum to the warp max (fminf guards -inf - -inf = nan; s==0 there)
    s0 *= __expf(fminf(m0 - M0, 0.f));
    s1 *= __expf(fminf(m1 - M1, 0.f));
    s2 *= __expf(fminf(m2 - M2, 0.f));
    s3 *= __expf(fminf(m3 - M3, 0.f));
    #pragma unroll
    for (int o = 16; o > 0; o >>= 1) {
        s0 += __shfl_xor_sync(0xffffffffu, s0, o);
        s1 += __shfl_xor_sync(0xffffffffu, s1, o);
        s2 += __shfl_xor_sync(0xffffffffu, s2, o);
        s3 += __shfl_xor_sync(0xffffffffu, s3, o);
    }
    if (lane == 0)
        *(float4*)&g_c[node * 4] = make_float4(M0 + logf(s0), M1 + logf(s1),
                                               M2 + logf(s2), M3 + logf(s3));
}

__device__ __forceinline__ float pick4(float4 v, int h) {
    float ab = (h & 1) ? v.y : v.x;
    float cd = (h & 1) ? v.w : v.z;
    return (h & 2) ? cd : ab;
}

// ====================== aggregation F=128 (warp per node, atomic-free) ======================
// lane owns features [lane*4, lane*4+4); head = lane>>3. alpha = exp(e - c). bias+relu fused.
__global__ void __launch_bounds__(256)
agg128_kernel(const float* __restrict__ bias) {
    int node = (blockIdx.x * blockDim.x + threadIdx.x) >> 5;
    int lane = threadIdx.x & 31;
    if (node >= NN) return;
    int r0 = g_rowptr[node], r1 = g_rowptr[node + 1];
    const int head = lane >> 3;

    float ch = pick4(*(const float4*)&g_c[node * 4], head);

    float4 acc = {0.f, 0.f, 0.f, 0.f};
    int i = r0;
    #pragma unroll 1
    for (; i + 7 < r1; i += 8) {
        int s[8];
        #pragma unroll
        for (int k = 0; k < 8; k++) s[k] = g_csrc[i + k];
        float a[8];
        #pragma unroll
        for (int k = 0; k < 8; k++) {
            float4 e4 = *(const float4*)&g_alpha[(long)(i + k) * 4];
            a[k] = __expf(pick4(e4, head) - ch);
        }
        float4 f[8];
        #pragma unroll
        for (int k = 0; k < 8; k++)
            f[k] = *(const float4*)&g_feat[(long)s[k] * 128 + lane * 4];
        #pragma unroll
        for (int k = 0; k < 8; k++) {
            acc.x += a[k] * f[k].x;
            acc.y += a[k] * f[k].y;
            acc.z += a[k] * f[k].z;
            acc.w += a[k] * f[k].w;
        }
    }
    for (; i < r1; i++) {
        int s = g_csrc[i];
        float4 e4 = *(const float4*)&g_alpha[(long)i * 4];
        float a = __expf(pick4(e4, head) - ch);
        float4 f = *(const float4*)&g_feat[(long)s * 128 + lane * 4];
        acc.x += a * f.x; acc.y += a * f.y; acc.z += a * f.z; acc.w += a * f.w;
    }
    float4 b = *(const float4*)&bias[lane * 4];
    acc.x = fmaxf(acc.x + b.x, 0.f);
    acc.y = fmaxf(acc.y + b.y, 0.f);
    acc.z = fmaxf(acc.z + b.z, 0.f);
    acc.w = fmaxf(acc.w + b.w, 0.f);
    *(float4*)&g_out[(long)node * 128 + lane * 4] = acc;
}

// ====================== aggregation F=188 (warp per node; no bias/act) ======================
__global__ void __launch_bounds__(256)
agg188_kernel() {
    int node = (blockIdx.x * blockDim.x + threadIdx.x) >> 5;
    int lane = threadIdx.x & 31;
    if (node >= NN) return;
    int r0 = g_rowptr[node], r1 = g_rowptr[node + 1];

    float4 c4 = *(const float4*)&g_c[node * 4];

    float acc[6] = {0.f, 0.f, 0.f, 0.f, 0.f, 0.f};
    int headk[6];
    #pragma unroll
    for (int k = 0; k < 6; k++) headk[k] = (lane + 32 * k) / CC;  // feature/47

    for (int i = r0; i < r1; i++) {
        int s = g_csrc[i];
        float4 e4 = *(const float4*)&g_alpha[(long)i * 4];
        float a0 = __expf(e4.x - c4.x);
        float a1 = __expf(e4.y - c4.y);
        float a2 = __expf(e4.z - c4.z);
        float a3 = __expf(e4.w - c4.w);
        float4 av = make_float4(a0, a1, a2, a3);
        const float* fs = g_feat + (long)s * 188;
        #pragma unroll
        for (int k = 0; k < 6; k++) {
            int j = lane + 32 * k;
            if (j < 188) acc[k] += pick4(av, headk[k]) * fs[j];
        }
    }
    float* op = g_out + (long)node * 188;
    #pragma unroll
    for (int k = 0; k < 6; k++) {
        int j = lane + 32 * k;
        if (j < 188) op[j] = acc[k];
    }
}

// ====================== final: head-mean (+bias) + log_softmax (warp per node) ======================
__global__ void __launch_bounds__(256)
final_kernel(const float* __restrict__ b3, float* __restrict__ y) {
    int node = (blockIdx.x * blockDim.x + threadIdx.x) >> 5;
    int lane = threadIdx.x & 31;
    if (node >= NN) return;
    const float* row = g_out + (long)node * HH * CC;

    float a0 = 0.f, a1 = 0.f;
    float v0 = -CUDART_INF_F, v1 = -CUDART_INF_F;
    if (lane < CC) {
        float sum = 0.f;
        #pragma unroll
        for (int h = 0; h < HH; h++) sum += row[h * CC + lane] + b3[h * CC + lane];
        a0 = sum * 0.25f; v0 = a0;
    }
    int c1 = lane + 32;
    if (c1 < CC) {
        float sum = 0.f;
        #pragma unroll
        for (int h = 0; h < HH; h++) sum += row[h * CC + c1] + b3[h * CC + c1];
        a1 = sum * 0.25f; v1 = a1;
    }
    float mx = fmaxf(v0, v1);
    #pragma unroll
    for (int o = 16; o > 0; o >>= 1) mx = fmaxf(mx, __shfl_xor_sync(0xffffffffu, mx, o));
    float s = 0.f;
    if (lane < CC) s += __expf(a0 - mx);
    if (c1 < CC)   s += __expf(a1 - mx);
    #pragma unroll
    for (int o = 16; o > 0; o >>= 1) s += __shfl_xor_sync(0xffffffffu, s, o);
    float lse = logf(s);
    if (lane < CC) y[(long)node * CC + lane] = a0 - mx - lse;
    if (c1 < CC)   y[(long)node * CC + c1] = a1 - mx - lse;
}

// ====================== host driver ======================
extern "C" void kernel_launch(void* const* d_in, const int* in_sizes, int n_in,
                              void* d_out, int out_size) {
    const float* x   = (const float*)d_in[0];
    const int*   src = (const int*)  d_in[1];
    const int*   dst = (const int*)  d_in[2];
    const float* W1  = (const float*)d_in[3];
    const float* al1 = (const float*)d_in[4];
    const float* ar1 = (const float*)d_in[5];
    const float* b1  = (const float*)d_in[6];
    const float* W2  = (const float*)d_in[7];
    const float* al2 = (const float*)d_in[8];
    const float* ar2 = (const float*)d_in[9];
    const float* b2  = (const float*)d_in[10];
    const float* W3  = (const float*)d_in[11];
    const float* al3 = (const float*)d_in[12];
    const float* ar3 = (const float*)d_in[13];
    const float* b3  = (const float*)d_in[14];
    float* y = (float*)d_out;

    static float* outb = nullptr;
    if (!outb) cudaGetSymbolAddress((void**)&outb, g_out);

    const int TB = 256;
    const int nodeWarpGrid = (NN + 7) / 8;

    // ---- CSR build (graph static across layers) ----
    zero2_kernel<<<(NN + TB - 1) / TB, TB>>>();
    hist_kernel<<<(EE + TB - 1) / TB, TB>>>(dst);
    scan_kernel<<<1, 1024>>>();
    scatter_kernel<<<(EE + TB - 1) / TB, TB>>>(src, dst);

    // ---- layer 1: x [N,256] -> g_out [N,128] ----
    {
        dim3 gg((NN + BM - 1) / BM, (128 + BN - 1) / BN);
        sgemm_kernel<<<gg, TB>>>(x, W1, NN, 128, F_IN);
        elr_kernel<<<(NN * HH + TB - 1) / TB, TB>>>(al1, ar1, DD);
        attn_softmax_kernel<<<nodeWarpGrid, TB>>>();
        agg128_kernel<<<nodeWarpGrid, TB>>>(b1);
    }
    // ---- layer 2: g_out [N,128] -> g_out [N,128] ----
    {
        dim3 gg((NN + BM - 1) / BM, (128 + BN - 1) / BN);
        sgemm_kernel<<<gg, TB>>>(outb, W2, NN, 128, 128);
        elr_kernel<<<(NN * HH + TB - 1) / TB, TB>>>(al2, ar2, DD);
        attn_softmax_kernel<<<nodeWarpGrid, TB>>>();
        agg128_kernel<<<nodeWarpGrid, TB>>>(b2);
    }
    // ---- layer 3: g_out [N,128] -> g_out [N,188] (bias fused into final) ----
    {
        dim3 gg((NN + BM - 1) / BM, (188 + BN - 1) / BN);
        sgemm_kernel<<<gg, TB>>>(outb, W3, NN, 188, 128);
        elr_kernel<<<(NN * HH + TB - 1) / TB, TB>>>(al3, ar3, CC);
        attn_softmax_kernel<<<nodeWarpGrid, TB>>>();
        agg188_kernel<<<nodeWarpGrid, TB>>>();
    }
    // ---- head-mean + bias + log_softmax ----
    final_kernel<<<(NN + 7) / 8, TB>>>(b3, y);
}